// round 15
// baseline (speedup 1.0000x reference)
#include <cuda_runtime.h>
#include <math.h>
#include <stdint.h>

#define Bv   64
#define Sv   512
#define Hv   256
#define G4   1024
#define Tv   9
#define NEGV (-100000.0f)
#define NBLK 128

typedef unsigned long long u64;

__device__ __forceinline__ void fma2(u64& d, u64 a, u64 b) {
    asm("fma.rn.f32x2 %0, %1, %2, %0;" : "+l"(d) : "l"(a), "l"(b));
}
__device__ __forceinline__ u64 pack2(float lo, float hi) {
    u64 r; asm("mov.b64 %0, {%1, %2};" : "=l"(r) : "f"(lo), "f"(hi)); return r;
}
__device__ __forceinline__ void unpack2(u64 v, float& lo, float& hi) {
    asm("mov.b64 {%0, %1}, %2;" : "=f"(lo), "=f"(hi) : "l"(v));
}
__device__ __forceinline__ float upsum(u64 v) {
    float lo, hi; unpack2(v, lo, hi); return lo + hi;
}
__device__ __forceinline__ void stream_bar(int id) {
    asm volatile("bar.sync %0, 128;" :: "r"(id) : "memory");
}
__device__ __forceinline__ void st_release(unsigned* p, unsigned v) {
    asm volatile("st.release.gpu.global.u32 [%0], %1;" :: "l"(p), "r"(v) : "memory");
}
__device__ __forceinline__ unsigned ld_acquire(unsigned* p) {
    unsigned v;
    asm volatile("ld.acquire.gpu.global.u32 %0, [%1];" : "=r"(v) : "l"(p) : "memory");
    return v;
}

// ---------------- device scratch ----------------
__device__ float g_G[(size_t)2 * Sv * G4 * Bv];     // [dir][s][row][b]
__device__ float g_out0[(size_t)Sv * 512 * Bv];     // [s][feat][b]
__device__ float g_out1[(size_t)Sv * 512 * Bv];     // [s][feat][b]
__device__ float g_hbuf[2 * 2 * Hv * Bv];           // [parity][dir][j][b]  (j-major!)
__device__ float g_feats[(size_t)Bv * Sv * Tv];     // [b][s][t]
__device__ float g_fwd[Bv];
__device__ float g_gold[Bv];
__device__ unsigned g_gf[8 * 32 * 8];               // [group(dir*4+bg)][member ug] padded
__device__ unsigned g_epoch;

// ---------------- input-projection GEMM (64 batch x 128 rows per block) ----
template<int K, bool GATHER>
__global__ void __launch_bounds__(256) proj_kernel(
    const int* __restrict__ tokens, const float* __restrict__ embp,
    const float* __restrict__ W, const float* __restrict__ bih,
    const float* __restrict__ bhh)
{
    __shared__ float Asm[16][68];
    __shared__ float Bsm[16][132];
    __shared__ const float* rowp[64];

    const int t = threadIdx.x, s = blockIdx.y, dir = blockIdx.z, rt = blockIdx.x;

    if (t == 0 && rt == 0 && s == 0 && dir == 0) atomicAdd(&g_epoch, 1024u);

    if (GATHER && t < 64) rowp[t] = embp + (size_t)tokens[t * Sv + s] * K;

    const int lb = t >> 2, kq = t & 3;          // A (gather path)
    const int akr = t >> 4, abq = (t & 15) * 4; // A (direct path)
    const int br = t >> 1, bh = t & 1;          // B
    const float* wrow = W + ((size_t)(dir * G4 + rt * 128 + br)) * K + bh * 8;

    u64 acc[4][4];
#pragma unroll
    for (int i = 0; i < 4; ++i)
#pragma unroll
        for (int r = 0; r < 4; ++r) acc[i][r] = 0ull;

    const int tb4 = (t & 15) * 4, tr8 = (t >> 4) * 8;
    if (GATHER) __syncthreads();

    for (int k0 = 0; k0 < K; k0 += 16) {
        float4 av, w0v, w1v;
        if (GATHER) av = *(const float4*)(rowp[lb] + k0 + kq * 4);
        else av = *(const float4*)(g_out0 + ((size_t)s * 512 + k0 + akr) * Bv + abq);
        w0v = *(const float4*)(wrow + k0);
        w1v = *(const float4*)(wrow + k0 + 4);
        __syncthreads();
        if (GATHER) {
            Asm[kq*4+0][lb] = av.x; Asm[kq*4+1][lb] = av.y;
            Asm[kq*4+2][lb] = av.z; Asm[kq*4+3][lb] = av.w;
        } else {
            *(float4*)&Asm[akr][abq] = av;
        }
        Bsm[bh*8+0][br] = w0v.x; Bsm[bh*8+1][br] = w0v.y;
        Bsm[bh*8+2][br] = w0v.z; Bsm[bh*8+3][br] = w0v.w;
        Bsm[bh*8+4][br] = w1v.x; Bsm[bh*8+5][br] = w1v.y;
        Bsm[bh*8+6][br] = w1v.z; Bsm[bh*8+7][br] = w1v.w;
        __syncthreads();
#pragma unroll
        for (int k = 0; k < 16; ++k) {
            float4 a = *(const float4*)&Asm[k][tb4];
            ulonglong2 b01 = *(const ulonglong2*)&Bsm[k][tr8];
            ulonglong2 b23 = *(const ulonglong2*)&Bsm[k][tr8 + 4];
            u64 ap;
            ap = pack2(a.x, a.x);
            fma2(acc[0][0], ap, b01.x); fma2(acc[0][1], ap, b01.y);
            fma2(acc[0][2], ap, b23.x); fma2(acc[0][3], ap, b23.y);
            ap = pack2(a.y, a.y);
            fma2(acc[1][0], ap, b01.x); fma2(acc[1][1], ap, b01.y);
            fma2(acc[1][2], ap, b23.x); fma2(acc[1][3], ap, b23.y);
            ap = pack2(a.z, a.z);
            fma2(acc[2][0], ap, b01.x); fma2(acc[2][1], ap, b01.y);
            fma2(acc[2][2], ap, b23.x); fma2(acc[2][3], ap, b23.y);
            ap = pack2(a.w, a.w);
            fma2(acc[3][0], ap, b01.x); fma2(acc[3][1], ap, b01.y);
            fma2(acc[3][2], ap, b23.x); fma2(acc[3][3], ap, b23.y);
        }
    }

    float* gout = g_G + ((size_t)(dir * Sv + s)) * G4 * Bv;
#pragma unroll
    for (int r = 0; r < 4; ++r) {
        int row0 = rt * 128 + tr8 + 2 * r;
        float bs0 = bih[dir * G4 + row0]     + bhh[dir * G4 + row0];
        float bs1 = bih[dir * G4 + row0 + 1] + bhh[dir * G4 + row0 + 1];
#pragma unroll
        for (int i = 0; i < 4; ++i) {
            float lo, hi; unpack2(acc[i][r], lo, hi);
            gout[(size_t)row0 * Bv + tb4 + i]       = lo + bs0;
            gout[(size_t)(row0 + 1) * Bv + tb4 + i] = hi + bs1;
        }
    }
}

// ---------------- persistent bidirectional LSTM layer (dual-stream) --------
// 128 blocks x 256 threads. Warps 0-3 = fwd stream, warps 4-7 = bwd stream.
// Each stream: 8 hidden units (ug = bid&31) x 16 batches (bg = bid>>5).
// g_hbuf is [parity][dir][j][b] so the per-step h store is coalesced.
#define HPAD 268
__global__ void __launch_bounds__(256, 1) lstm_kernel(const float* __restrict__ whh, int sel)
{
    extern __shared__ float sm[];
    float* wsm = sm;                    // [2][32 rows = unit*4+gate][256]
    float* hsm = sm + 2 * 32 * 256;     // [2][16][HPAD]

    const int tid = threadIdx.x;
    const int bid = blockIdx.x;
    const int dir = tid >> 7;          // stream id = direction
    const int st  = tid & 127;         // thread within stream
    const int ug  = bid & 31;          // unit group (8 units)
    const int bg  = bid >> 5;          // batch group (16 batches)
    const int gi  = dir * 4 + bg;      // sync group id (8 groups of 32)
    const int tb  = st & 15;
    const int tj  = st >> 4;           // 0..7
    const int j   = ug * 8 + tj;       // global hidden unit
    const int B   = bg * 16 + tb;      // global batch
    const int bar = 1 + dir;

    const unsigned base = g_epoch;
    float* outp = sel ? g_out1 : g_out0;
    float* wst = wsm + dir * 32 * 256;
    float* hst = hsm + dir * 16 * HPAD;

    // stream W_hh slice -> smem: 32 rows x 256 floats
    for (int q = st; q < 2048; q += 128) {
        int row = q >> 6;              // 0..31 = unit*4+gate
        int unit = row >> 2, gate = row & 3;
        int kk = (q & 63) * 4;
        *(float4*)(wst + row * 256 + kk) =
            *(const float4*)(whh + ((size_t)(dir * G4 + gate * Hv + ug * 8 + unit)) * Hv + kk);
    }

    // zero own (j,B) cell of parity-0
    __stcg(&g_hbuf[dir * 16384 + j * 64 + B], 0.f);

    float c = 0.f;
    int p = 0;

    // initial group sync
    stream_bar(bar);
    if (st == 0) st_release(&g_gf[(gi * 32 + ug) * 8], base + 1);
    if (st < 32) { while (ld_acquire(&g_gf[(gi * 32 + st) * 8]) < base + 1) {} }
    stream_bar(bar);

    const int tstep = dir ? -1 : 1;
    int t = dir ? (Sv - 1) : 0;
    const float* gb = g_G + ((size_t)(dir * Sv + t) * G4) * Bv + B;
    float a0 = __ldg(gb + (size_t)(0 * Hv + j) * Bv);
    float a1 = __ldg(gb + (size_t)(1 * Hv + j) * Bv);
    float a2 = __ldg(gb + (size_t)(2 * Hv + j) * Bv);
    float a3 = __ldg(gb + (size_t)(3 * Hv + j) * Bv);

    for (int step = 0; step < Sv; ++step) {
        // stage stream's h tile: read [j][B-slice] (8x64B per warp), transpose to hsm[b][j]
        const float* hg = g_hbuf + p * 32768 + dir * 16384 + bg * 16;
#pragma unroll
        for (int q = 0; q < 8; ++q) {
            int idx = st + q * 128;         // 0..1023
            int jr = idx >> 2;              // 0..255
            int quad = idx & 3;             // 0..3
            float4 v = __ldcg((const float4*)(hg + jr * 64 + quad * 4));
            float* dst = hst + jr;
            dst[(quad * 4 + 0) * HPAD] = v.x;
            dst[(quad * 4 + 1) * HPAD] = v.y;
            dst[(quad * 4 + 2) * HPAD] = v.z;
            dst[(quad * 4 + 3) * HPAD] = v.w;
        }
        stream_bar(bar);

        u64 A0 = pack2(a0, 0.f), A1 = pack2(a1, 0.f);
        u64 A2 = pack2(a2, 0.f), A3 = pack2(a3, 0.f);
        const ulonglong2* hv = (const ulonglong2*)(hst + tb * HPAD);
        const ulonglong2* w0 = (const ulonglong2*)(wst + (tj * 4 + 0) * 256);
        const ulonglong2* w1 = (const ulonglong2*)(wst + (tj * 4 + 1) * 256);
        const ulonglong2* w2 = (const ulonglong2*)(wst + (tj * 4 + 2) * 256);
        const ulonglong2* w3 = (const ulonglong2*)(wst + (tj * 4 + 3) * 256);

#pragma unroll 8
        for (int kc = 0; kc < 64; ++kc) {
            ulonglong2 h2 = hv[kc];
            ulonglong2 w;
            w = w0[kc]; fma2(A0, h2.x, w.x); fma2(A0, h2.y, w.y);
            w = w1[kc]; fma2(A1, h2.x, w.x); fma2(A1, h2.y, w.y);
            w = w2[kc]; fma2(A2, h2.x, w.x); fma2(A2, h2.y, w.y);
            w = w3[kc]; fma2(A3, h2.x, w.x); fma2(A3, h2.y, w.y);
        }

        float s0 = upsum(A0), s1 = upsum(A1), s2 = upsum(A2), s3 = upsum(A3);
        float gi_ = 1.f / (1.f + expf(-s0));
        float gf_ = 1.f / (1.f + expf(-s1));
        float gg  = tanhf(s2);
        float go  = 1.f / (1.f + expf(-s3));
        c = gf_ * c + gi_ * gg;
        float hval = go * tanhf(c);

        // coalesced h store (2 x 64B per warp), then publish
        __stcg(&g_hbuf[(p ^ 1) * 32768 + dir * 16384 + j * 64 + B], hval);
        stream_bar(bar);
        unsigned target = base + 2 + step;
        if (st == 0) st_release(&g_gf[(gi * 32 + ug) * 8], target);

        // off-critical-path work while peers publish:
        outp[((size_t)t * 512 + dir * Hv + j) * Bv + B] = hval;
        int tn = t + tstep;
        if (step + 1 < Sv) {
            const float* gn = g_G + ((size_t)(dir * Sv + tn) * G4) * Bv + B;
            a0 = __ldg(gn + (size_t)(0 * Hv + j) * Bv);
            a1 = __ldg(gn + (size_t)(1 * Hv + j) * Bv);
            a2 = __ldg(gn + (size_t)(2 * Hv + j) * Bv);
            a3 = __ldg(gn + (size_t)(3 * Hv + j) * Bv);
        }
        p ^= 1;
        t = tn;

        if (st < 32) { while (ld_acquire(&g_gf[(gi * 32 + st) * 8]) < target) {} }
        stream_bar(bar);
    }
}

// ---------------- fc: feats[b][s][t], out1 layout [s][feat][b] -------------
__global__ void __launch_bounds__(64) feats_kernel(
    const float* __restrict__ fcw, const float* __restrict__ fcb)
{
    __shared__ float wsh[9 * 512];
    const int s = blockIdx.x, b = threadIdx.x;
    for (int q = b; q < 9 * 512; q += 64) wsh[q] = fcw[q];
    __syncthreads();

    float pp[9];
#pragma unroll
    for (int i = 0; i < 9; ++i) pp[i] = 0.f;
    const float* col = g_out1 + (size_t)s * 512 * Bv + b;
#pragma unroll 4
    for (int k = 0; k < 512; ++k) {
        float x = col[(size_t)k * Bv];
#pragma unroll
        for (int tt = 0; tt < 9; ++tt) pp[tt] = fmaf(x, wsh[tt * 512 + k], pp[tt]);
    }
#pragma unroll
    for (int tt = 0; tt < 9; ++tt)
        g_feats[((size_t)b * Sv + s) * Tv + tt] = pp[tt] + fcb[tt];
}

// ---------------- CRF forward + gold (one warp per batch element) ----------
__global__ void __launch_bounds__(32) crf_kernel(
    const int* __restrict__ tags, const int* __restrict__ lens,
    const float* __restrict__ trans)
{
    const int b = blockIdx.x, lane = threadIdx.x;
    const float* fb = g_feats + (size_t)b * Sv * Tv;
    const int* tg = tags + b * Sv;
    const int L = lens[b];

    float body = 0.f;
    for (int pp = lane; pp < Sv - 1; pp += 32)
        if (pp + 1 < L) {
            int t0 = tg[pp], t1 = tg[pp + 1];
            body += trans[t0 * Tv + t1] + fb[pp * Tv + t1];
        }
#pragma unroll
    for (int o = 16; o; o >>= 1) body += __shfl_xor_sync(0xffffffffu, body, o);
    if (lane == 0)
        g_gold[b] = trans[7 * Tv + tg[0]] + fb[tg[0]] + body + trans[tg[L - 1] * Tv + 8];

    float trc[9];
#pragma unroll
    for (int i = 0; i < 9; ++i)
        trc[i] = (lane < 9) ? trans[i * Tv + lane] : NEGV;
    float alpha = (lane == 7) ? 0.f : NEGV;

    for (int t = 0; t < Sv; ++t) {
        float av[9];
#pragma unroll
        for (int i = 0; i < 9; ++i) av[i] = __shfl_sync(0xffffffffu, alpha, i);
        float m = NEGV * 4.f;
#pragma unroll
        for (int i = 0; i < 9; ++i) m = fmaxf(m, av[i] + trc[i]);
        float ssum = 0.f;
#pragma unroll
        for (int i = 0; i < 9; ++i) ssum += expf(av[i] + trc[i] - m);
        float ft = (lane < 9) ? fb[t * Tv + lane] : 0.f;
        float nv = m + logf(ssum) + ft;
        if (t < L) alpha = nv;
    }

    float v = (lane < 9) ? alpha + trans[lane * Tv + 8] : NEGV * 4.f;
    float av[9];
#pragma unroll
    for (int i = 0; i < 9; ++i) av[i] = __shfl_sync(0xffffffffu, v, i);
    if (lane == 0) {
        float m = av[0];
#pragma unroll
        for (int i = 1; i < 9; ++i) m = fmaxf(m, av[i]);
        float ssum = 0.f;
#pragma unroll
        for (int i = 0; i < 9; ++i) ssum += expf(av[i] - m);
        g_fwd[b] = m + logf(ssum);
    }
}

__global__ void reduce_kernel(float* out)
{
    if (threadIdx.x == 0) {
        float s = 0.f;
        for (int b = 0; b < Bv; ++b) s += g_fwd[b] - g_gold[b];
        out[0] = s / (float)Bv;
    }
}

// ---------------- launch ----------------
extern "C" void kernel_launch(void* const* d_in, const int* in_sizes, int n_in,
                              void* d_out, int out_size)
{
    (void)in_sizes; (void)n_in; (void)out_size;
    const int*   tokens = (const int*)d_in[0];
    const int*   tags   = (const int*)d_in[1];
    const int*   lens   = (const int*)d_in[2];
    const float* emb    = (const float*)d_in[3];
    const float* w_ih0  = (const float*)d_in[4];
    const float* w_hh0  = (const float*)d_in[5];
    const float* b_ih0  = (const float*)d_in[6];
    const float* b_hh0  = (const float*)d_in[7];
    const float* w_ih1  = (const float*)d_in[8];
    const float* w_hh1  = (const float*)d_in[9];
    const float* b_ih1  = (const float*)d_in[10];
    const float* b_hh1  = (const float*)d_in[11];
    const float* fc_w   = (const float*)d_in[12];
    const float* fc_b   = (const float*)d_in[13];
    const float* trans  = (const float*)d_in[14];
    float* out = (float*)d_out;

    const int lstm_smem = (2 * 32 * 256 + 2 * 16 * HPAD) * 4;
    cudaFuncSetAttribute(lstm_kernel,
        cudaFuncAttributeMaxDynamicSharedMemorySize, lstm_smem);

    dim3 pg(8, 512, 2);
    proj_kernel<256, true><<<pg, 256>>>(tokens, emb, w_ih0, b_ih0, b_hh0);
    lstm_kernel<<<NBLK, 256, lstm_smem>>>(w_hh0, 0);
    proj_kernel<512, false><<<pg, 256>>>(nullptr, nullptr, w_ih1, b_ih1, b_hh1);
    lstm_kernel<<<NBLK, 256, lstm_smem>>>(w_hh1, 1);
    feats_kernel<<<Sv, 64>>>(fc_w, fc_b);
    crf_kernel<<<Bv, 32>>>(tags, lens, trans);
    reduce_kernel<<<1, 32>>>(out);
}

// round 16
// speedup vs baseline: 1.0738x; 1.0738x over previous
#include <cuda_runtime.h>
#include <math.h>
#include <stdint.h>

#define Bv   64
#define Sv   512
#define Hv   256
#define G4   1024
#define Tv   9
#define NEGV (-100000.0f)
#define NBLK 128

typedef unsigned long long u64;

__device__ __forceinline__ void fma2(u64& d, u64 a, u64 b) {
    asm("fma.rn.f32x2 %0, %1, %2, %0;" : "+l"(d) : "l"(a), "l"(b));
}
__device__ __forceinline__ u64 pack2(float lo, float hi) {
    u64 r; asm("mov.b64 %0, {%1, %2};" : "=l"(r) : "f"(lo), "f"(hi)); return r;
}
__device__ __forceinline__ void unpack2(u64 v, float& lo, float& hi) {
    asm("mov.b64 {%0, %1}, %2;" : "=f"(lo), "=f"(hi) : "l"(v));
}
__device__ __forceinline__ float upsum(u64 v) {
    float lo, hi; unpack2(v, lo, hi); return lo + hi;
}
__device__ __forceinline__ void stream_bar(int id) {
    asm volatile("bar.sync %0, 128;" :: "r"(id) : "memory");
}
__device__ __forceinline__ void st_release(unsigned* p, unsigned v) {
    asm volatile("st.release.gpu.global.u32 [%0], %1;" :: "l"(p), "r"(v) : "memory");
}
__device__ __forceinline__ unsigned ld_acquire(unsigned* p) {
    unsigned v;
    asm volatile("ld.acquire.gpu.global.u32 %0, [%1];" : "=r"(v) : "l"(p) : "memory");
    return v;
}

// ---------------- device scratch ----------------
__device__ float g_G[(size_t)2 * Sv * G4 * Bv];     // [dir][s][row][b]
__device__ float g_out0[(size_t)Sv * 512 * Bv];     // [s][feat][b]
__device__ float g_out1[(size_t)Sv * 512 * Bv];     // [s][feat][b]
__device__ float g_hbuf[2 * 2 * Bv * Hv];           // [parity][dir][b][k]
__device__ float g_feats[(size_t)Bv * Sv * Tv];     // [b][s][t]
__device__ float g_fwd[Bv];
__device__ float g_gold[Bv];
__device__ unsigned g_gf[8 * 32 * 8];               // [group(dir*4+bg)][member ug] padded
__device__ unsigned g_epoch;

// ---------------- input-projection GEMM (64 batch x 128 rows per block) ----
template<int K, bool GATHER>
__global__ void __launch_bounds__(256) proj_kernel(
    const int* __restrict__ tokens, const float* __restrict__ embp,
    const float* __restrict__ W, const float* __restrict__ bih,
    const float* __restrict__ bhh)
{
    __shared__ float Asm[16][68];
    __shared__ float Bsm[16][132];
    __shared__ const float* rowp[64];

    const int t = threadIdx.x, s = blockIdx.y, dir = blockIdx.z, rt = blockIdx.x;

    if (t == 0 && rt == 0 && s == 0 && dir == 0) atomicAdd(&g_epoch, 1024u);

    if (GATHER && t < 64) rowp[t] = embp + (size_t)tokens[t * Sv + s] * K;

    const int lb = t >> 2, kq = t & 3;          // A (gather path)
    const int akr = t >> 4, abq = (t & 15) * 4; // A (direct path)
    const int br = t >> 1, bh = t & 1;          // B
    const float* wrow = W + ((size_t)(dir * G4 + rt * 128 + br)) * K + bh * 8;

    u64 acc[4][4];
#pragma unroll
    for (int i = 0; i < 4; ++i)
#pragma unroll
        for (int r = 0; r < 4; ++r) acc[i][r] = 0ull;

    const int tb4 = (t & 15) * 4, tr8 = (t >> 4) * 8;
    if (GATHER) __syncthreads();

    for (int k0 = 0; k0 < K; k0 += 16) {
        float4 av, w0v, w1v;
        if (GATHER) av = *(const float4*)(rowp[lb] + k0 + kq * 4);
        else av = *(const float4*)(g_out0 + ((size_t)s * 512 + k0 + akr) * Bv + abq);
        w0v = *(const float4*)(wrow + k0);
        w1v = *(const float4*)(wrow + k0 + 4);
        __syncthreads();
        if (GATHER) {
            Asm[kq*4+0][lb] = av.x; Asm[kq*4+1][lb] = av.y;
            Asm[kq*4+2][lb] = av.z; Asm[kq*4+3][lb] = av.w;
        } else {
            *(float4*)&Asm[akr][abq] = av;
        }
        Bsm[bh*8+0][br] = w0v.x; Bsm[bh*8+1][br] = w0v.y;
        Bsm[bh*8+2][br] = w0v.z; Bsm[bh*8+3][br] = w0v.w;
        Bsm[bh*8+4][br] = w1v.x; Bsm[bh*8+5][br] = w1v.y;
        Bsm[bh*8+6][br] = w1v.z; Bsm[bh*8+7][br] = w1v.w;
        __syncthreads();
#pragma unroll
        for (int k = 0; k < 16; ++k) {
            float4 a = *(const float4*)&Asm[k][tb4];
            ulonglong2 b01 = *(const ulonglong2*)&Bsm[k][tr8];
            ulonglong2 b23 = *(const ulonglong2*)&Bsm[k][tr8 + 4];
            u64 ap;
            ap = pack2(a.x, a.x);
            fma2(acc[0][0], ap, b01.x); fma2(acc[0][1], ap, b01.y);
            fma2(acc[0][2], ap, b23.x); fma2(acc[0][3], ap, b23.y);
            ap = pack2(a.y, a.y);
            fma2(acc[1][0], ap, b01.x); fma2(acc[1][1], ap, b01.y);
            fma2(acc[1][2], ap, b23.x); fma2(acc[1][3], ap, b23.y);
            ap = pack2(a.z, a.z);
            fma2(acc[2][0], ap, b01.x); fma2(acc[2][1], ap, b01.y);
            fma2(acc[2][2], ap, b23.x); fma2(acc[2][3], ap, b23.y);
            ap = pack2(a.w, a.w);
            fma2(acc[3][0], ap, b01.x); fma2(acc[3][1], ap, b01.y);
            fma2(acc[3][2], ap, b23.x); fma2(acc[3][3], ap, b23.y);
        }
    }

    float* gout = g_G + ((size_t)(dir * Sv + s)) * G4 * Bv;
#pragma unroll
    for (int r = 0; r < 4; ++r) {
        int row0 = rt * 128 + tr8 + 2 * r;
        float bs0 = bih[dir * G4 + row0]     + bhh[dir * G4 + row0];
        float bs1 = bih[dir * G4 + row0 + 1] + bhh[dir * G4 + row0 + 1];
#pragma unroll
        for (int i = 0; i < 4; ++i) {
            float lo, hi; unpack2(acc[i][r], lo, hi);
            gout[(size_t)row0 * Bv + tb4 + i]       = lo + bs0;
            gout[(size_t)(row0 + 1) * Bv + tb4 + i] = hi + bs1;
        }
    }
}

// ---------------- persistent bidirectional LSTM layer (dual-stream) --------
// 128 blocks x 256 threads. Warps 0-3 = fwd stream, warps 4-7 = bwd stream.
// Each stream: 8 hidden units (ug = bid&31) x 16 batches (bg = bid>>5).
// Identical to the 8080us R14 kernel EXCEPT the publish path:
//   threadfence+volatile -> st.release.gpu / ld.acquire.gpu, and the outp
//   DRAM store + g_G prefetch moved after the flag publish.
__global__ void __launch_bounds__(256, 1) lstm_kernel(const float* __restrict__ whh, int sel)
{
    extern __shared__ float sm[];
    float* wsm = sm;                    // [2][32 rows = unit*4+gate][256]
    float* hsm = sm + 2 * 32 * 256;     // [2][16][260]

    const int tid = threadIdx.x;
    const int bid = blockIdx.x;
    const int dir = tid >> 7;          // stream id = direction
    const int st  = tid & 127;         // thread within stream
    const int ug  = bid & 31;          // unit group (8 units)
    const int bg  = bid >> 5;          // batch group (16 batches)
    const int gi  = dir * 4 + bg;      // sync group id (8 groups of 32)
    const int tb  = st & 15;
    const int tj  = st >> 4;           // 0..7
    const int j   = ug * 8 + tj;       // global hidden unit
    const int B   = bg * 16 + tb;      // global batch
    const int bar = 1 + dir;

    const unsigned base = g_epoch;
    float* outp = sel ? g_out1 : g_out0;
    float* wst = wsm + dir * 32 * 256;
    float* hst = hsm + dir * 16 * 260;

    // stream W_hh slice -> smem: 32 rows x 256 floats
    for (int q = st; q < 2048; q += 128) {
        int row = q >> 6;              // 0..31 = unit*4+gate
        int unit = row >> 2, gate = row & 3;
        int kk = (q & 63) * 4;
        *(float4*)(wst + row * 256 + kk) =
            *(const float4*)(whh + ((size_t)(dir * G4 + gate * Hv + ug * 8 + unit)) * Hv + kk);
    }

    // zero this stream's parity-0 read region (redundant across group, same value)
    {
        float4 z = make_float4(0.f, 0.f, 0.f, 0.f);
        float* zb = g_hbuf + dir * 16384 + bg * 4096;
#pragma unroll
        for (int q = 0; q < 8; ++q)
            __stcg((float4*)(zb + (st + q * 128) * 4), z);
    }

    float c = 0.f;
    int p = 0;

    // initial group sync
    stream_bar(bar);
    if (st == 0) st_release(&g_gf[(gi * 32 + ug) * 8], base + 1);
    if (st < 32) { while (ld_acquire(&g_gf[(gi * 32 + st) * 8]) < base + 1) {} }
    stream_bar(bar);

    const int tstep = dir ? -1 : 1;
    int t = dir ? (Sv - 1) : 0;
    const float* gb = g_G + ((size_t)(dir * Sv + t) * G4) * Bv + B;
    float a0 = __ldg(gb + (size_t)(0 * Hv + j) * Bv);
    float a1 = __ldg(gb + (size_t)(1 * Hv + j) * Bv);
    float a2 = __ldg(gb + (size_t)(2 * Hv + j) * Bv);
    float a3 = __ldg(gb + (size_t)(3 * Hv + j) * Bv);

    for (int step = 0; step < Sv; ++step) {
        // stage stream's 16-batch h tile (1024 float4, 128 threads)
        const float* hg = g_hbuf + p * 32768 + dir * 16384 + bg * 4096;
#pragma unroll
        for (int q = 0; q < 8; ++q) {
            int idx = st + q * 128;
            int bl = idx >> 6, kq = (idx & 63) * 4;
            *(float4*)(hst + bl * 260 + kq) = __ldcg((const float4*)(hg + bl * 256 + kq));
        }
        stream_bar(bar);

        u64 A0 = pack2(a0, 0.f), A1 = pack2(a1, 0.f);
        u64 A2 = pack2(a2, 0.f), A3 = pack2(a3, 0.f);
        const ulonglong2* hv = (const ulonglong2*)(hst + tb * 260);
        const ulonglong2* w0 = (const ulonglong2*)(wst + (tj * 4 + 0) * 256);
        const ulonglong2* w1 = (const ulonglong2*)(wst + (tj * 4 + 1) * 256);
        const ulonglong2* w2 = (const ulonglong2*)(wst + (tj * 4 + 2) * 256);
        const ulonglong2* w3 = (const ulonglong2*)(wst + (tj * 4 + 3) * 256);

#pragma unroll 8
        for (int kc = 0; kc < 64; ++kc) {
            ulonglong2 h2 = hv[kc];
            ulonglong2 w;
            w = w0[kc]; fma2(A0, h2.x, w.x); fma2(A0, h2.y, w.y);
            w = w1[kc]; fma2(A1, h2.x, w.x); fma2(A1, h2.y, w.y);
            w = w2[kc]; fma2(A2, h2.x, w.x); fma2(A2, h2.y, w.y);
            w = w3[kc]; fma2(A3, h2.x, w.x); fma2(A3, h2.y, w.y);
        }

        float s0 = upsum(A0), s1 = upsum(A1), s2 = upsum(A2), s3 = upsum(A3);
        float gi_ = 1.f / (1.f + expf(-s0));
        float gf_ = 1.f / (1.f + expf(-s1));
        float gg  = tanhf(s2);
        float go  = 1.f / (1.f + expf(-s3));
        c = gf_ * c + gi_ * gg;
        float hval = go * tanhf(c);

        // h store, then publish immediately (release covers all warps' stores
        // via the named barrier); DRAM traffic goes after the publish.
        __stcg(&g_hbuf[(p ^ 1) * 32768 + dir * 16384 + B * 256 + j], hval);
        stream_bar(bar);
        unsigned target = base + 2 + step;
        if (st == 0) st_release(&g_gf[(gi * 32 + ug) * 8], target);

        // off-critical-path: layer output store + next-step gate prefetch
        outp[((size_t)t * 512 + dir * Hv + j) * Bv + B] = hval;
        int tn = t + tstep;
        if (step + 1 < Sv) {
            const float* gn = g_G + ((size_t)(dir * Sv + tn) * G4) * Bv + B;
            a0 = __ldg(gn + (size_t)(0 * Hv + j) * Bv);
            a1 = __ldg(gn + (size_t)(1 * Hv + j) * Bv);
            a2 = __ldg(gn + (size_t)(2 * Hv + j) * Bv);
            a3 = __ldg(gn + (size_t)(3 * Hv + j) * Bv);
        }
        p ^= 1;
        t = tn;

        if (st < 32) { while (ld_acquire(&g_gf[(gi * 32 + st) * 8]) < target) {} }
        stream_bar(bar);
    }
}

// ---------------- fc: feats[b][s][t], out1 layout [s][feat][b] -------------
__global__ void __launch_bounds__(64) feats_kernel(
    const float* __restrict__ fcw, const float* __restrict__ fcb)
{
    __shared__ float wsh[9 * 512];
    const int s = blockIdx.x, b = threadIdx.x;
    for (int q = b; q < 9 * 512; q += 64) wsh[q] = fcw[q];
    __syncthreads();

    float pp[9];
#pragma unroll
    for (int i = 0; i < 9; ++i) pp[i] = 0.f;
    const float* col = g_out1 + (size_t)s * 512 * Bv + b;
#pragma unroll 4
    for (int k = 0; k < 512; ++k) {
        float x = col[(size_t)k * Bv];
#pragma unroll
        for (int tt = 0; tt < 9; ++tt) pp[tt] = fmaf(x, wsh[tt * 512 + k], pp[tt]);
    }
#pragma unroll
    for (int tt = 0; tt < 9; ++tt)
        g_feats[((size_t)b * Sv + s) * Tv + tt] = pp[tt] + fcb[tt];
}

// ---------------- CRF forward + gold (one warp per batch element) ----------
__global__ void __launch_bounds__(32) crf_kernel(
    const int* __restrict__ tags, const int* __restrict__ lens,
    const float* __restrict__ trans)
{
    const int b = blockIdx.x, lane = threadIdx.x;
    const float* fb = g_feats + (size_t)b * Sv * Tv;
    const int* tg = tags + b * Sv;
    const int L = lens[b];

    float body = 0.f;
    for (int pp = lane; pp < Sv - 1; pp += 32)
        if (pp + 1 < L) {
            int t0 = tg[pp], t1 = tg[pp + 1];
            body += trans[t0 * Tv + t1] + fb[pp * Tv + t1];
        }
#pragma unroll
    for (int o = 16; o; o >>= 1) body += __shfl_xor_sync(0xffffffffu, body, o);
    if (lane == 0)
        g_gold[b] = trans[7 * Tv + tg[0]] + fb[tg[0]] + body + trans[tg[L - 1] * Tv + 8];

    float trc[9];
#pragma unroll
    for (int i = 0; i < 9; ++i)
        trc[i] = (lane < 9) ? trans[i * Tv + lane] : NEGV;
    float alpha = (lane == 7) ? 0.f : NEGV;

    for (int t = 0; t < Sv; ++t) {
        float av[9];
#pragma unroll
        for (int i = 0; i < 9; ++i) av[i] = __shfl_sync(0xffffffffu, alpha, i);
        float m = NEGV * 4.f;
#pragma unroll
        for (int i = 0; i < 9; ++i) m = fmaxf(m, av[i] + trc[i]);
        float ssum = 0.f;
#pragma unroll
        for (int i = 0; i < 9; ++i) ssum += expf(av[i] + trc[i] - m);
        float ft = (lane < 9) ? fb[t * Tv + lane] : 0.f;
        float nv = m + logf(ssum) + ft;
        if (t < L) alpha = nv;
    }

    float v = (lane < 9) ? alpha + trans[lane * Tv + 8] : NEGV * 4.f;
    float av[9];
#pragma unroll
    for (int i = 0; i < 9; ++i) av[i] = __shfl_sync(0xffffffffu, v, i);
    if (lane == 0) {
        float m = av[0];
#pragma unroll
        for (int i = 1; i < 9; ++i) m = fmaxf(m, av[i]);
        float ssum = 0.f;
#pragma unroll
        for (int i = 0; i < 9; ++i) ssum += expf(av[i] - m);
        g_fwd[b] = m + logf(ssum);
    }
}

__global__ void reduce_kernel(float* out)
{
    if (threadIdx.x == 0) {
        float s = 0.f;
        for (int b = 0; b < Bv; ++b) s += g_fwd[b] - g_gold[b];
        out[0] = s / (float)Bv;
    }
}

// ---------------- launch ----------------
extern "C" void kernel_launch(void* const* d_in, const int* in_sizes, int n_in,
                              void* d_out, int out_size)
{
    (void)in_sizes; (void)n_in; (void)out_size;
    const int*   tokens = (const int*)d_in[0];
    const int*   tags   = (const int*)d_in[1];
    const int*   lens   = (const int*)d_in[2];
    const float* emb    = (const float*)d_in[3];
    const float* w_ih0  = (const float*)d_in[4];
    const float* w_hh0  = (const float*)d_in[5];
    const float* b_ih0  = (const float*)d_in[6];
    const float* b_hh0  = (const float*)d_in[7];
    const float* w_ih1  = (const float*)d_in[8];
    const float* w_hh1  = (const float*)d_in[9];
    const float* b_ih1  = (const float*)d_in[10];
    const float* b_hh1  = (const float*)d_in[11];
    const float* fc_w   = (const float*)d_in[12];
    const float* fc_b   = (const float*)d_in[13];
    const float* trans  = (const float*)d_in[14];
    float* out = (float*)d_out;

    const int lstm_smem = (2 * 32 * 256 + 2 * 16 * 260) * 4;
    cudaFuncSetAttribute(lstm_kernel,
        cudaFuncAttributeMaxDynamicSharedMemorySize, lstm_smem);

    dim3 pg(8, 512, 2);
    proj_kernel<256, true><<<pg, 256>>>(tokens, emb, w_ih0, b_ih0, b_hh0);
    lstm_kernel<<<NBLK, 256, lstm_smem>>>(w_hh0, 0);
    proj_kernel<512, false><<<pg, 256>>>(nullptr, nullptr, w_ih1, b_ih1, b_hh1);
    lstm_kernel<<<NBLK, 256, lstm_smem>>>(w_hh1, 1);
    feats_kernel<<<Sv, 64>>>(fc_w, fc_b);
    crf_kernel<<<Bv, 32>>>(tags, lens, trans);
    reduce_kernel<<<1, 32>>>(out);
}